// round 1
// baseline (speedup 1.0000x reference)
#include <cuda_runtime.h>
#include <cuda_bf16.h>

#define D        256
#define DQ       64          // D/4 (float4 quads per row)
#define KCODES   8192
#define BM       64          // rows per block
#define BN       64          // codes per chunk
#define BSTRIDE  260         // padded floats per B row in smem (1040B = 65*16, float4-aligned)
#define THREADS  256

__device__ float g_c2[KCODES];

// packed dual-FMA: acc.{lo,hi} += a.{lo,hi} * b.{lo,hi}
#define FMA2(acc, a, b) \
    asm volatile("fma.rn.f32x2 %0, %1, %2, %0;" : "+l"(acc) : "l"(a), "l"(b))

__device__ __forceinline__ float pairsum(unsigned long long v) {
    return __uint_as_float((unsigned)v) + __uint_as_float((unsigned)(v >> 32));
}

// ---------------- kernel 1: codebook squared norms ----------------
__global__ void c2_kernel(const float* __restrict__ cb) {
    int warp = (blockIdx.x * blockDim.x + threadIdx.x) >> 5;
    int lane = threadIdx.x & 31;
    if (warp >= KCODES) return;
    const float4* row = (const float4*)(cb + (size_t)warp * D);
    float4 a = row[lane];
    float4 b = row[lane + 32];
    float s = a.x*a.x + a.y*a.y + a.z*a.z + a.w*a.w
            + b.x*b.x + b.y*b.y + b.z*b.z + b.w*b.w;
    #pragma unroll
    for (int off = 16; off; off >>= 1) s += __shfl_down_sync(0xffffffffu, s, off);
    if (lane == 0) g_c2[warp] = s;
}

// ---------------- kernel 2: argmin GEMM + gather ----------------
extern __shared__ float smem[];

__global__ __launch_bounds__(THREADS, 1)
void vq_kernel(const float* __restrict__ h, const float* __restrict__ cb,
               float* __restrict__ outQ, float* __restrict__ outIdxF,
               int* __restrict__ outIdxI)
{
    float* As   = smem;                       // BM * D
    float* Bs   = As + BM * D;                // BN * BSTRIDE
    float* c2s  = Bs + BN * BSTRIDE;          // BN
    int*   sIdx = (int*)(c2s + BN);           // BM

    const int tid  = threadIdx.x;
    const int row0 = blockIdx.x * BM;
    const int cg   = tid & 7;    // col group: cols = cg + 8*j, j=0..7
    const int rg   = tid >> 3;   // row group: rows = rg*2 + {0,1}  (rg 0..31)

    // ---- load A tile (64 rows x 256 f32 = 64KB), coalesced float4 ----
    const float4* h4  = (const float4*)(h + (size_t)row0 * D);
    float4*       As4 = (float4*)As;
    #pragma unroll
    for (int i = 0; i < 16; i++) {
        int lin = i * THREADS + tid;      // 0..4095
        As4[lin] = h4[lin];
    }

    float best0 = 3.4e38f, best1 = 3.4e38f;
    int   bidx0 = 0,       bidx1 = 0;

    const float4* cb4 = (const float4*)cb;

    for (int n0 = 0; n0 < KCODES; n0 += BN) {
        __syncthreads();   // previous chunk's compute done before overwriting Bs
        // ---- load B chunk (64 codes x 256 f32) into padded smem ----
        #pragma unroll
        for (int i = 0; i < 16; i++) {
            int lin = i * THREADS + tid;
            int r   = lin >> 6;           // code within chunk
            int dq  = lin & 63;           // quad within row
            float4 v = cb4[(size_t)(n0 + r) * DQ + dq];
            *(float4*)(Bs + r * BSTRIDE + dq * 4) = v;
        }
        if (tid < BN) c2s[tid] = g_c2[n0 + tid];
        __syncthreads();

        // ---- 2 rows x 8 cols register tile, packed f32x2 accumulation ----
        unsigned long long acc[2][8][2];
        #pragma unroll
        for (int i = 0; i < 2; i++)
            #pragma unroll
            for (int j = 0; j < 8; j++) { acc[i][j][0] = 0ull; acc[i][j][1] = 0ull; }

        const ulonglong2* a0 = (const ulonglong2*)(As + (rg * 2 + 0) * D);
        const ulonglong2* a1 = (const ulonglong2*)(As + (rg * 2 + 1) * D);

        #pragma unroll 4
        for (int dq = 0; dq < DQ; dq++) {
            ulonglong2 av0 = a0[dq];
            ulonglong2 av1 = a1[dq];
            #pragma unroll
            for (int j = 0; j < 8; j++) {
                ulonglong2 bv = *(const ulonglong2*)(Bs + (cg + 8 * j) * BSTRIDE + dq * 4);
                FMA2(acc[0][j][0], av0.x, bv.x);
                FMA2(acc[0][j][1], av0.y, bv.y);
                FMA2(acc[1][j][0], av1.x, bv.x);
                FMA2(acc[1][j][1], av1.y, bv.y);
            }
        }

        // ---- epilogue: score = c2 - 2*dot, keep running argmin ----
        #pragma unroll
        for (int j = 0; j < 8; j++) {
            int   col = cg + 8 * j;
            float cc  = c2s[col];
            float dot0 = pairsum(acc[0][j][0]) + pairsum(acc[0][j][1]);
            float dot1 = pairsum(acc[1][j][0]) + pairsum(acc[1][j][1]);
            float s0 = fmaf(-2.0f, dot0, cc);
            float s1 = fmaf(-2.0f, dot1, cc);
            if (s0 < best0) { best0 = s0; bidx0 = n0 + col; }
            if (s1 < best1) { best1 = s1; bidx1 = n0 + col; }
        }
    }

    // ---- reduce argmin across the 8 col-group lanes (same rows) ----
    #pragma unroll
    for (int off = 4; off; off >>= 1) {
        float ob0 = __shfl_down_sync(0xffffffffu, best0, off, 8);
        int   oi0 = __shfl_down_sync(0xffffffffu, bidx0, off, 8);
        float ob1 = __shfl_down_sync(0xffffffffu, best1, off, 8);
        int   oi1 = __shfl_down_sync(0xffffffffu, bidx1, off, 8);
        if (ob0 < best0 || (ob0 == best0 && oi0 < bidx0)) { best0 = ob0; bidx0 = oi0; }
        if (ob1 < best1 || (ob1 == best1 && oi1 < bidx1)) { best1 = ob1; bidx1 = oi1; }
    }
    __syncthreads();
    if (cg == 0) { sIdx[rg * 2] = bidx0; sIdx[rg * 2 + 1] = bidx1; }
    __syncthreads();

    // ---- gather winning codebook rows -> output ----
    if (outQ) {
        float4* outQ4 = (float4*)(outQ + (size_t)row0 * D);
        #pragma unroll
        for (int i = 0; i < 16; i++) {
            int lin = i * THREADS + tid;
            int r = lin >> 6, dq = lin & 63;
            outQ4[lin] = cb4[(size_t)sIdx[r] * DQ + dq];
        }
    }
    if (outIdxF && tid < BM) outIdxF[row0 + tid] = (float)sIdx[tid];
    if (outIdxI && tid < BM) outIdxI[row0 + tid] = sIdx[tid];
}

// ---------------- launch ----------------
extern "C" void kernel_launch(void* const* d_in, const int* in_sizes, int n_in,
                              void* d_out, int out_size)
{
    const float* h  = (const float*)d_in[0];
    const float* cb = (const float*)d_in[1];
    const int N = in_sizes[0] / D;           // 32768 rows

    c2_kernel<<<KCODES / 8, 256>>>(cb);

    size_t smemBytes = (size_t)(BM * D + BN * BSTRIDE + BN) * 4 + BM * 4;
    cudaFuncSetAttribute(vq_kernel, cudaFuncAttributeMaxDynamicSharedMemorySize,
                         (int)smemBytes);

    // Output layout defense: q [N*D] f32, optionally followed by idx [N];
    // if out_size is only N, the output is idx alone (int32).
    float* outQ    = nullptr;
    float* outIdxF = nullptr;
    int*   outIdxI = nullptr;
    long long nd = (long long)N * D;
    if (out_size >= nd) {
        outQ = (float*)d_out;
        if (out_size >= nd + N) outIdxF = (float*)d_out + nd;
    } else {
        outIdxI = (int*)d_out;
    }

    vq_kernel<<<N / BM, THREADS, smemBytes>>>(h, cb, outQ, outIdxF, outIdxI);
}

// round 5
// speedup vs baseline: 8.1415x; 8.1415x over previous
#include <cuda_runtime.h>
#include <cuda_bf16.h>
#include <cstdint>

#define D        256
#define KCODES   8192
#define BM       256                 // rows per CTA (8 warps x 2 m16 tiles)
#define BN       64                  // codes per chunk
#define NCHUNK   (KCODES / BN)
#define THREADS  256
#define NROWS    32768

// ---- smem: double-buffered f32 B chunk + c2 ----
#define BSTRIDE   264                              // f32 per B row (1056B = 66*16)
#define BUF_BYTES (BN * BSTRIDE * 4)               // 67584
#define C2_OFF    (2 * BUF_BYTES)                  // [2][64] f32
#define SMEM_TOTAL (C2_OFF + 2 * BN * 4 + 256)

__device__ __align__(16) float g_c2[KCODES];
__device__ int g_cand[NROWS * 8];

// ======================= helpers =======================
__device__ __forceinline__ uint32_t smem_u32(const void* p) {
    uint32_t a;
    asm("{ .reg .u64 t; cvta.to.shared.u64 t, %1; cvt.u32.u64 %0, t; }" : "=r"(a) : "l"(p));
    return a;
}
__device__ __forceinline__ uint32_t packbf(float lo, float hi) {
    uint32_t r;
    asm("cvt.rn.bf16x2.f32 %0, %1, %2;" : "=r"(r) : "f"(hi), "f"(lo));
    return r;
}

#define CP_ASYNC16(dst, src) \
    asm volatile("cp.async.ca.shared.global [%0], [%1], 16;" :: "r"(dst), "l"(src))
#define CP_COMMIT() asm volatile("cp.async.commit_group;" ::: "memory")
#define CP_WAIT1()  asm volatile("cp.async.wait_group 1;" ::: "memory")

#define MMA_BF16(Cr, Ar, Br) \
    asm volatile("mma.sync.aligned.m16n8k16.row.col.f32.bf16.bf16.f32 " \
        "{%0,%1,%2,%3}, {%4,%5,%6,%7}, {%8,%9}, {%0,%1,%2,%3};" \
        : "+f"((Cr)[0]), "+f"((Cr)[1]), "+f"((Cr)[2]), "+f"((Cr)[3]) \
        : "r"((Ar)[0]), "r"((Ar)[1]), "r"((Ar)[2]), "r"((Ar)[3]), \
          "r"((Br)[0]), "r"((Br)[1]))

// ---------------- kernel 1: codebook squared norms ----------------
__global__ void c2_kernel(const float* __restrict__ cb) {
    int warp = (blockIdx.x * blockDim.x + threadIdx.x) >> 5;
    int lane = threadIdx.x & 31;
    if (warp >= KCODES) return;
    const float4* row = (const float4*)(cb + (size_t)warp * D);
    float4 a = row[lane];
    float4 b = row[lane + 32];
    float s = a.x*a.x + a.y*a.y + a.z*a.z + a.w*a.w
            + b.x*b.x + b.y*b.y + b.z*b.z + b.w*b.w;
    #pragma unroll
    for (int off = 16; off; off >>= 1) s += __shfl_down_sync(0xffffffffu, s, off);
    if (lane == 0) g_c2[warp] = s;
}

// ---------------- kernel 2: bf16 HMMA candidate search ----------------
extern __shared__ char smem_raw[];

__device__ __forceinline__ void load_chunk_async(uint32_t sbase, int buf,
                                                 const float* __restrict__ cb,
                                                 int n0, int tid) {
    uint32_t dstb = sbase + buf * BUF_BYTES;
    #pragma unroll
    for (int i = 0; i < 16; i++) {
        int e = i * THREADS + tid;            // 0..4095 16B-units (64 rows x 64 units)
        int n = e >> 6, k16 = e & 63;         // 64 units (=256 f32) per row
        uint32_t dst = dstb + n * (BSTRIDE * 4) + k16 * 16;
        const float* src = cb + (size_t)(n0 + n) * D + k16 * 4;
        CP_ASYNC16(dst, src);
    }
    if (tid < 16) {
        uint32_t dst = sbase + C2_OFF + buf * 256 + tid * 16;
        CP_ASYNC16(dst, (const float*)g_c2 + n0 + tid * 4);
    }
}

__global__ __launch_bounds__(THREADS, 1)
void vq_main(const float* __restrict__ h, const float* __restrict__ cb)
{
    const uint32_t sbase = smem_u32(smem_raw);
    const float* c2s = (const float*)(smem_raw + C2_OFF);
    const int tid  = threadIdx.x;
    const int lane = tid & 31;
    const int wid  = tid >> 5;
    const int rowbase = blockIdx.x * BM + wid * 32;

    // ---- A fragments: 2 m16-tiles x 16 ksteps x 4 regs (bf16x2), loaded once ----
    uint32_t a[2][16][4];
    #pragma unroll
    for (int mt = 0; mt < 2; mt++) {
        #pragma unroll
        for (int k = 0; k < 16; k++) {
            int r = rowbase + mt * 16 + (lane >> 2);
            int c = k * 16 + (lane & 3) * 2;
            const float* p0 = h + (size_t)r * D + c;
            const float* p1 = h + (size_t)(r + 8) * D + c;
            float2 v00 = *(const float2*)p0;
            float2 v01 = *(const float2*)(p0 + 8);
            float2 v10 = *(const float2*)p1;
            float2 v11 = *(const float2*)(p1 + 8);
            a[mt][k][0] = packbf(v00.x, v00.y);
            a[mt][k][1] = packbf(v10.x, v10.y);
            a[mt][k][2] = packbf(v01.x, v01.y);
            a[mt][k][3] = packbf(v11.x, v11.y);
        }
    }

    // ---- per-lane top-2 for 4 row-slots ----
    float t1v[4], t2v[4];
    int   t1i[4], t2i[4];
    #pragma unroll
    for (int s = 0; s < 4; s++) { t1v[s] = 3.4e38f; t2v[s] = 3.4e38f; t1i[s] = 0; t2i[s] = 0; }

    // ---- prologue: chunk 0 in flight ----
    load_chunk_async(sbase, 0, cb, 0, tid);
    CP_COMMIT();

    for (int ch = 0; ch < NCHUNK; ch++) {
        const int buf = ch & 1;
        const int n0  = ch * BN;

        __syncthreads();   // everyone done computing on buf^1 before we overwrite it
        if (ch + 1 < NCHUNK) load_chunk_async(sbase, buf ^ 1, cb, n0 + BN, tid);
        CP_COMMIT();
        CP_WAIT1();        // chunk ch's group complete
        __syncthreads();

        const char*  bs  = smem_raw + buf * BUF_BYTES;
        const float* c2p = c2s + buf * BN;

        #pragma unroll
        for (int pr = 0; pr < 4; pr++) {            // 16 cols per pair
            float C[4][4];
            #pragma unroll
            for (int q = 0; q < 4; q++)
                #pragma unroll
                for (int e = 0; e < 4; e++) C[q][e] = 0.0f;

            #pragma unroll
            for (int k = 0; k < 16; k++) {
                uint32_t b[2][2];
                #pragma unroll
                for (int nh = 0; nh < 2; nh++) {
                    int n  = pr * 16 + nh * 8 + (lane >> 2);
                    int kd = k * 16 + (lane & 3) * 2;
                    const char* p = bs + n * (BSTRIDE * 4) + kd * 4;
                    float2 f0 = *(const float2*)p;          // kd, kd+1
                    float2 f1 = *(const float2*)(p + 32);   // kd+8, kd+9
                    b[nh][0] = packbf(f0.x, f0.y);
                    b[nh][1] = packbf(f1.x, f1.y);
                }
                #pragma unroll
                for (int mt = 0; mt < 2; mt++)
                    #pragma unroll
                    for (int nh = 0; nh < 2; nh++)
                        MMA_BF16(C[mt * 2 + nh], a[mt][k], b[nh]);
            }

            // epilogue: score = c2 - 2*dot, top-2 insert
            #pragma unroll
            for (int mt = 0; mt < 2; mt++) {
                #pragma unroll
                for (int nh = 0; nh < 2; nh++) {
                    const float* f = C[mt * 2 + nh];
                    int lc = pr * 16 + nh * 8 + (lane & 3) * 2;
                    int gi = n0 + lc;
                    float ca = c2p[lc], cb2 = c2p[lc + 1];
                    float s0a = fmaf(-2.0f, f[0], ca);
                    float s0b = fmaf(-2.0f, f[1], cb2);
                    float s1a = fmaf(-2.0f, f[2], ca);
                    float s1b = fmaf(-2.0f, f[3], cb2);
                    int sl0 = mt * 2, sl1 = mt * 2 + 1;
                    if (s0a < t1v[sl0]) { t2v[sl0]=t1v[sl0]; t2i[sl0]=t1i[sl0]; t1v[sl0]=s0a; t1i[sl0]=gi; }
                    else if (s0a < t2v[sl0]) { t2v[sl0]=s0a; t2i[sl0]=gi; }
                    if (s0b < t1v[sl0]) { t2v[sl0]=t1v[sl0]; t2i[sl0]=t1i[sl0]; t1v[sl0]=s0b; t1i[sl0]=gi+1; }
                    else if (s0b < t2v[sl0]) { t2v[sl0]=s0b; t2i[sl0]=gi+1; }
                    if (s1a < t1v[sl1]) { t2v[sl1]=t1v[sl1]; t2i[sl1]=t1i[sl1]; t1v[sl1]=s1a; t1i[sl1]=gi; }
                    else if (s1a < t2v[sl1]) { t2v[sl1]=s1a; t2i[sl1]=gi; }
                    if (s1b < t1v[sl1]) { t2v[sl1]=t1v[sl1]; t2i[sl1]=t1i[sl1]; t1v[sl1]=s1b; t1i[sl1]=gi+1; }
                    else if (s1b < t2v[sl1]) { t2v[sl1]=s1b; t2i[sl1]=gi+1; }
                }
            }
        }
    }

    // ---- publish 8 candidates per row (4 lanes x top-2) ----
    #pragma unroll
    for (int s = 0; s < 4; s++) {
        int row  = rowbase + (s >> 1) * 16 + (lane >> 2) + (s & 1) * 8;
        int base = row * 8 + (lane & 3) * 2;
        g_cand[base]     = t1i[s];
        g_cand[base + 1] = t2i[s];
    }
}

// ---------------- kernel 3: exact fp32 rescore + gather ----------------
__global__ __launch_bounds__(256)
void rescore_kernel(const float* __restrict__ h, const float* __restrict__ cb,
                    float* __restrict__ outQ, float* __restrict__ outIdxF,
                    int* __restrict__ outIdxI)
{
    const int row  = blockIdx.x * 8 + (threadIdx.x >> 5);
    const int lane = threadIdx.x & 31;

    const float4* hr = (const float4*)(h + (size_t)row * D);
    float4 h0 = hr[lane], h1 = hr[lane + 32];

    float bd = 3.4e38f;
    int   bi = KCODES;
    #pragma unroll
    for (int j = 0; j < 8; j++) {
        int ci = g_cand[row * 8 + j];
        const float4* cr = (const float4*)(cb + (size_t)ci * D);
        float4 c0 = cr[lane], c1 = cr[lane + 32];
        float dot = h0.x*c0.x + h0.y*c0.y + h0.z*c0.z + h0.w*c0.w
                  + h1.x*c1.x + h1.y*c1.y + h1.z*c1.z + h1.w*c1.w;
        #pragma unroll
        for (int o = 16; o; o >>= 1) dot += __shfl_xor_sync(0xffffffffu, dot, o);
        float dist = fmaf(-2.0f, dot, g_c2[ci]);
        if (dist < bd || (dist == bd && ci < bi)) { bd = dist; bi = ci; }
    }

    const float4* wr = (const float4*)(cb + (size_t)bi * D);
    if (outQ) {
        float4* o4 = (float4*)(outQ + (size_t)row * D);
        o4[lane]      = wr[lane];
        o4[lane + 32] = wr[lane + 32];
    }
    if (lane == 0) {
        if (outIdxF) outIdxF[row] = (float)bi;
        if (outIdxI) outIdxI[row] = bi;
    }
}

// ---------------- launch ----------------
extern "C" void kernel_launch(void* const* d_in, const int* in_sizes, int n_in,
                              void* d_out, int out_size)
{
    const float* h  = (const float*)d_in[0];
    const float* cb = (const float*)d_in[1];
    const int N = in_sizes[0] / D;   // 32768 rows

    c2_kernel<<<KCODES / 8, 256>>>(cb);

    cudaFuncSetAttribute(vq_main, cudaFuncAttributeMaxDynamicSharedMemorySize,
                         SMEM_TOTAL);
    vq_main<<<N / BM, THREADS, SMEM_TOTAL>>>(h, cb);

    float* outQ    = nullptr;
    float* outIdxF = nullptr;
    int*   outIdxI = nullptr;
    long long nd = (long long)N * D;
    if (out_size >= nd) {
        outQ = (float*)d_out;
        if (out_size >= nd + N) outIdxF = (float*)d_out + nd;
    } else {
        outIdxI = (int*)d_out;
    }

    rescore_kernel<<<N / 8, 256>>>(h, cb, outQ, outIdxF, outIdxI);
}

// round 6
// speedup vs baseline: 9.2113x; 1.1314x over previous
#include <cuda_runtime.h>
#include <cuda_bf16.h>
#include <cstdint>

#define D        256
#define KCODES   8192
#define BM       256                 // rows per CTA (8 warps x 2 m16 tiles)
#define BN       64                  // codes per chunk
#define NCHUNK   (KCODES / BN)
#define THREADS  256
#define NROWS    32768

// ---- smem: double-buffered bf16 B chunk + c2 ----
#define BROWB     528                              // bytes per B row (512 data + 16 pad)
#define BUF_BYTES (BN * BROWB)                     // 33792
#define C2_OFF    (2 * BUF_BYTES)                  // [2][64] f32
#define SMEM_TOTAL (C2_OFF + 2 * BN * 4 + 256)

__device__ __align__(16) float g_c2[KCODES];
__device__ __align__(16) __nv_bfloat16 g_cbh[KCODES * D];   // bf16 codebook (4MB)
__device__ int g_cand[NROWS * 8];

// ======================= helpers =======================
__device__ __forceinline__ uint32_t smem_u32(const void* p) {
    uint32_t a;
    asm("{ .reg .u64 t; cvta.to.shared.u64 t, %1; cvt.u32.u64 %0, t; }" : "=r"(a) : "l"(p));
    return a;
}
__device__ __forceinline__ uint32_t packbf(float lo, float hi) {
    uint32_t r;
    asm("cvt.rn.bf16x2.f32 %0, %1, %2;" : "=r"(r) : "f"(hi), "f"(lo));
    return r;
}

#define CP_ASYNC16(dst, src) \
    asm volatile("cp.async.ca.shared.global [%0], [%1], 16;" :: "r"(dst), "l"(src))
#define CP_COMMIT() asm volatile("cp.async.commit_group;" ::: "memory")
#define CP_WAIT1()  asm volatile("cp.async.wait_group 1;" ::: "memory")

#define MMA_BF16(Cr, Ar, B0, B1) \
    asm volatile("mma.sync.aligned.m16n8k16.row.col.f32.bf16.bf16.f32 " \
        "{%0,%1,%2,%3}, {%4,%5,%6,%7}, {%8,%9}, {%0,%1,%2,%3};" \
        : "+f"((Cr)[0]), "+f"((Cr)[1]), "+f"((Cr)[2]), "+f"((Cr)[3]) \
        : "r"((Ar)[0]), "r"((Ar)[1]), "r"((Ar)[2]), "r"((Ar)[3]), \
          "r"(B0), "r"(B1))

#define LDSM_X4(r0, r1, r2, r3, addr) \
    asm volatile("ldmatrix.sync.aligned.m8n8.x4.shared.b16 {%0,%1,%2,%3}, [%4];" \
        : "=r"(r0), "=r"(r1), "=r"(r2), "=r"(r3) : "r"(addr))

// ---------------- kernel 0: codebook f32 -> bf16 ----------------
__global__ void cvt_kernel(const float* __restrict__ cb) {
    int t = blockIdx.x * blockDim.x + threadIdx.x;   // 0..262143
    const float4* s4 = (const float4*)cb;            // 2 f32 pairs per float4
    float4 v0 = s4[t * 2];
    float4 v1 = s4[t * 2 + 1];
    uint2 o;
    o.x = packbf(v0.x, v0.y);
    o.y = packbf(v0.z, v0.w);
    uint2 o2;
    o2.x = packbf(v1.x, v1.y);
    o2.y = packbf(v1.z, v1.w);
    uint4* d = (uint4*)g_cbh;
    d[t] = make_uint4(o.x, o.y, o2.x, o2.y);
}

// ---------------- kernel 1: codebook squared norms (exact f32) ----------------
__global__ void c2_kernel(const float* __restrict__ cb) {
    int warp = (blockIdx.x * blockDim.x + threadIdx.x) >> 5;
    int lane = threadIdx.x & 31;
    if (warp >= KCODES) return;
    const float4* row = (const float4*)(cb + (size_t)warp * D);
    float4 a = row[lane];
    float4 b = row[lane + 32];
    float s = a.x*a.x + a.y*a.y + a.z*a.z + a.w*a.w
            + b.x*b.x + b.y*b.y + b.z*b.z + b.w*b.w;
    #pragma unroll
    for (int off = 16; off; off >>= 1) s += __shfl_down_sync(0xffffffffu, s, off);
    if (lane == 0) g_c2[warp] = s;
}

// ---------------- kernel 2: bf16 HMMA candidate search ----------------
extern __shared__ char smem_raw[];

__device__ __forceinline__ void load_chunk_async(uint32_t sbase, int buf,
                                                 int n0, int tid) {
    uint32_t dstb = sbase + buf * BUF_BYTES;
    const __nv_bfloat16* cbh = g_cbh;
    #pragma unroll
    for (int i = 0; i < 8; i++) {
        int e = i * THREADS + tid;            // 0..2047 16B-units (64 rows x 32 units)
        int n = e >> 5, u = e & 31;           // 32 units (=256 bf16) per row
        uint32_t dst = dstb + n * BROWB + u * 16;
        const __nv_bfloat16* src = cbh + (size_t)(n0 + n) * D + u * 8;
        CP_ASYNC16(dst, src);
    }
    if (tid < 16) {
        uint32_t dst = sbase + C2_OFF + buf * 256 + tid * 16;
        CP_ASYNC16(dst, (const float*)g_c2 + n0 + tid * 4);
    }
}

__global__ __launch_bounds__(THREADS, 1)
void vq_main(const float* __restrict__ h)
{
    const uint32_t sbase = smem_u32(smem_raw);
    const float* c2s = (const float*)(smem_raw + C2_OFF);
    const int tid  = threadIdx.x;
    const int lane = tid & 31;
    const int wid  = tid >> 5;
    const int rowbase = blockIdx.x * BM + wid * 32;

    // ---- A fragments: 2 m16-tiles x 16 ksteps x 4 regs (bf16x2), loaded once ----
    uint32_t a[2][16][4];
    #pragma unroll
    for (int mt = 0; mt < 2; mt++) {
        #pragma unroll
        for (int k = 0; k < 16; k++) {
            int r = rowbase + mt * 16 + (lane >> 2);
            int c = k * 16 + (lane & 3) * 2;
            const float* p0 = h + (size_t)r * D + c;
            const float* p1 = h + (size_t)(r + 8) * D + c;
            float2 v00 = *(const float2*)p0;
            float2 v01 = *(const float2*)(p0 + 8);
            float2 v10 = *(const float2*)p1;
            float2 v11 = *(const float2*)(p1 + 8);
            a[mt][k][0] = packbf(v00.x, v00.y);
            a[mt][k][1] = packbf(v10.x, v10.y);
            a[mt][k][2] = packbf(v01.x, v01.y);
            a[mt][k][3] = packbf(v11.x, v11.y);
        }
    }

    // per-lane ldmatrix address offset: matrices (n0k0, n0k1, n1k0, n1k1)
    // lane L: n = ((L>>4)&1)*8 + (L&7), kbyte = ((L>>3)&1)*16
    const uint32_t laneoff = (uint32_t)((((lane >> 4) & 1) * 8 + (lane & 7)) * BROWB
                                        + ((lane >> 3) & 1) * 16);

    // ---- per-lane top-2 for 4 row-slots ----
    float t1v[4], t2v[4];
    int   t1i[4], t2i[4];
    #pragma unroll
    for (int s = 0; s < 4; s++) { t1v[s] = 3.4e38f; t2v[s] = 3.4e38f; t1i[s] = 0; t2i[s] = 0; }

    // ---- prologue: chunk 0 in flight ----
    load_chunk_async(sbase, 0, 0, tid);
    CP_COMMIT();

    for (int ch = 0; ch < NCHUNK; ch++) {
        const int buf = ch & 1;
        const int n0  = ch * BN;

        __syncthreads();
        if (ch + 1 < NCHUNK) load_chunk_async(sbase, buf ^ 1, n0 + BN, tid);
        CP_COMMIT();
        CP_WAIT1();
        __syncthreads();

        const uint32_t bsm = sbase + buf * BUF_BYTES + laneoff;
        const float* c2p = c2s + buf * BN;

        #pragma unroll
        for (int pr = 0; pr < 4; pr++) {            // 16 cols per pr
            float C[4][4];
            #pragma unroll
            for (int q = 0; q < 4; q++)
                #pragma unroll
                for (int e = 0; e < 4; e++) C[q][e] = 0.0f;

            const uint32_t bpr = bsm + (uint32_t)(pr * 16) * BROWB;
            #pragma unroll
            for (int k = 0; k < 16; k++) {
                uint32_t b0, b1, b2, b3;
                LDSM_X4(b0, b1, b2, b3, bpr + k * 32);
                MMA_BF16(C[0], a[0][k], b0, b1);
                MMA_BF16(C[1], a[0][k], b2, b3);
                MMA_BF16(C[2], a[1][k], b0, b1);
                MMA_BF16(C[3], a[1][k], b2, b3);
            }

            // epilogue: score = c2 - 2*dot, top-2 insert
            #pragma unroll
            for (int mt = 0; mt < 2; mt++) {
                #pragma unroll
                for (int nh = 0; nh < 2; nh++) {
                    const float* f = C[mt * 2 + nh];
                    int lc = pr * 16 + nh * 8 + (lane & 3) * 2;
                    int gi = n0 + lc;
                    float ca = c2p[lc], cb2 = c2p[lc + 1];
                    float s0a = fmaf(-2.0f, f[0], ca);
                    float s0b = fmaf(-2.0f, f[1], cb2);
                    float s1a = fmaf(-2.0f, f[2], ca);
                    float s1b = fmaf(-2.0f, f[3], cb2);
                    int sl0 = mt * 2, sl1 = mt * 2 + 1;
                    if (s0a < t1v[sl0]) { t2v[sl0]=t1v[sl0]; t2i[sl0]=t1i[sl0]; t1v[sl0]=s0a; t1i[sl0]=gi; }
                    else if (s0a < t2v[sl0]) { t2v[sl0]=s0a; t2i[sl0]=gi; }
                    if (s0b < t1v[sl0]) { t2v[sl0]=t1v[sl0]; t2i[sl0]=t1i[sl0]; t1v[sl0]=s0b; t1i[sl0]=gi+1; }
                    else if (s0b < t2v[sl0]) { t2v[sl0]=s0b; t2i[sl0]=gi+1; }
                    if (s1a < t1v[sl1]) { t2v[sl1]=t1v[sl1]; t2i[sl1]=t1i[sl1]; t1v[sl1]=s1a; t1i[sl1]=gi; }
                    else if (s1a < t2v[sl1]) { t2v[sl1]=s1a; t2i[sl1]=gi; }
                    if (s1b < t1v[sl1]) { t2v[sl1]=t1v[sl1]; t2i[sl1]=t1i[sl1]; t1v[sl1]=s1b; t1i[sl1]=gi+1; }
                    else if (s1b < t2v[sl1]) { t2v[sl1]=s1b; t2i[sl1]=gi+1; }
                }
            }
        }
    }

    // ---- publish 8 candidates per row (4 lanes x top-2) ----
    #pragma unroll
    for (int s = 0; s < 4; s++) {
        int row  = rowbase + (s >> 1) * 16 + (lane >> 2) + (s & 1) * 8;
        int base = row * 8 + (lane & 3) * 2;
        g_cand[base]     = t1i[s];
        g_cand[base + 1] = t2i[s];
    }
}

// ---------------- kernel 3: exact fp32 rescore + gather ----------------
__global__ __launch_bounds__(256)
void rescore_kernel(const float* __restrict__ h, const float* __restrict__ cb,
                    float* __restrict__ outQ, float* __restrict__ outIdxF,
                    int* __restrict__ outIdxI)
{
    const int row  = blockIdx.x * 8 + (threadIdx.x >> 5);
    const int lane = threadIdx.x & 31;

    const float4* hr = (const float4*)(h + (size_t)row * D);
    float4 h0 = hr[lane], h1 = hr[lane + 32];

    float bd = 3.4e38f;
    int   bi = KCODES;
    #pragma unroll
    for (int j = 0; j < 8; j++) {
        int ci = g_cand[row * 8 + j];
        const float4* cr = (const float4*)(cb + (size_t)ci * D);
        float4 c0 = cr[lane], c1 = cr[lane + 32];
        float dot = h0.x*c0.x + h0.y*c0.y + h0.z*c0.z + h0.w*c0.w
                  + h1.x*c1.x + h1.y*c1.y + h1.z*c1.z + h1.w*c1.w;
        #pragma unroll
        for (int o = 16; o; o >>= 1) dot += __shfl_xor_sync(0xffffffffu, dot, o);
        float dist = fmaf(-2.0f, dot, g_c2[ci]);
        if (dist < bd || (dist == bd && ci < bi)) { bd = dist; bi = ci; }
    }

    const float4* wr = (const float4*)(cb + (size_t)bi * D);
    if (outQ) {
        float4* o4 = (float4*)(outQ + (size_t)row * D);
        o4[lane]      = wr[lane];
        o4[lane + 32] = wr[lane + 32];
    }
    if (lane == 0) {
        if (outIdxF) outIdxF[row] = (float)bi;
        if (outIdxI) outIdxI[row] = bi;
    }
}

// ---------------- launch ----------------
extern "C" void kernel_launch(void* const* d_in, const int* in_sizes, int n_in,
                              void* d_out, int out_size)
{
    const float* h  = (const float*)d_in[0];
    const float* cb = (const float*)d_in[1];
    const int N = in_sizes[0] / D;   // 32768 rows

    cvt_kernel<<<KCODES * D / 8 / 256, 256>>>(cb);
    c2_kernel<<<KCODES / 8, 256>>>(cb);

    cudaFuncSetAttribute(vq_main, cudaFuncAttributeMaxDynamicSharedMemorySize,
                         SMEM_TOTAL);
    vq_main<<<N / BM, THREADS, SMEM_TOTAL>>>(h);

    float* outQ    = nullptr;
    float* outIdxF = nullptr;
    int*   outIdxI = nullptr;
    long long nd = (long long)N * D;
    if (out_size >= nd) {
        outQ = (float*)d_out;
        if (out_size >= nd + N) outIdxF = (float*)d_out + nd;
    } else {
        outIdxI = (int*)d_out;
    }

    rescore_kernel<<<N / 8, 256>>>(h, cb, outQ, outIdxF, outIdxI);
}